// round 5
// baseline (speedup 1.0000x reference)
#include <cuda_runtime.h>
#include <math.h>

// Problem constants
constexpr int cB = 8;
constexpr int cR = 64;
constexpr int cC = 16;
constexpr int cD = 128;
constexpr int cN = 2016;          // R*(R-1)/2
constexpr int cCD = cC * cD;      // 2048
constexpr int cP = 16;            // pairs per CTA
constexpr int cTILES = cN / cP;   // 126
constexpr int NT = 512;           // 16 warps

// Scratch (allocation-free rule: __device__ globals)
__device__ float g_Yh[(size_t)cB * cR * cCD];   // batch @ hW          (4MB)
__device__ float g_Yg[(size_t)cB * cR * cCD];   // batch @ gW + gb     (4MB)
__device__ float g_Km[(size_t)cB * cR * cCD];   // batch @ kW + kb     (4MB)

// Shared memory layout (float offsets)
constexpr int OFF_WS  = 0;                  // 64x128 float2 paired weights (16384 floats)
constexpr int OFF_XS  = OFF_WS + cD * cD;   // 16384 : P*CD tile (x_mid -> q -> x_final)
constexpr int OFF_AL  = OFF_XS + cP * cCD;  // 49152 : alpha P*R (raw dots)
constexpr int OFF_AL2 = OFF_AL + cP * cR;   // 50176 : alpha duplicated float2 (2048 floats)
constexpr int OFF_HB  = OFF_AL2 + cP * cR * 2;  // 52224
constexpr int OFF_QB  = OFF_HB + cD;
constexpr int OFF_S1B = OFF_QB + cD;
constexpr int OFF_S2W = OFF_S1B + cD;
constexpr int OFF_MSK = OFF_S2W + cD;
constexpr int OFF_SC  = OFF_MSK + cC;
constexpr int OFF_RI  = OFF_SC + cP;
constexpr int OFF_CI  = OFF_RI + cP;
constexpr int OFF_S2B = OFF_CI + cP;
constexpr int SMEM_FLOATS = OFF_S2B + 8;
constexpr int SMEM_BYTES  = SMEM_FLOATS * 4;   // ~211 KB

typedef unsigned long long u64;

__device__ __forceinline__ float sigmoidf_(float x) { return 1.0f / (1.0f + __expf(-x)); }

__device__ __forceinline__ float2 upk2(u64 v) {
    float2 f; asm("mov.b64 {%0,%1},%2;" : "=f"(f.x), "=f"(f.y) : "l"(v)); return f;
}
__device__ __forceinline__ u64 ffma2(u64 a, u64 b, u64 c) {
    u64 d; asm("fma.rn.f32x2 %0,%1,%2,%3;" : "=l"(d) : "l"(a), "l"(b), "l"(c)); return d;
}

// ---------------------------------------------------------------------------
// Kernel 1: precompute Yh = batch@hW, Yg = batch@gW + gb, Km = batch@kW + kb
// ---------------------------------------------------------------------------
__global__ __launch_bounds__(128) void phylo_precompute(
    const float* __restrict__ batch,
    const float* __restrict__ hW,
    const float* __restrict__ gW, const float* __restrict__ gb,
    const float* __restrict__ kW, const float* __restrict__ kb)
{
    __shared__ float xs[cCD];
    const int br  = blockIdx.x;
    const int tid = threadIdx.x;
    const float* src = batch + (size_t)br * cCD;
    for (int i = tid; i < cCD; i += 128) xs[i] = src[i];
    __syncthreads();

    const int d = tid;
    float accH[cC], accG[cC], accK[cC];
    const float gbd = gb[d], kbd = kb[d];
#pragma unroll
    for (int c = 0; c < cC; c++) { accH[c] = 0.0f; accG[c] = gbd; accK[c] = kbd; }

    for (int kk = 0; kk < cD; kk++) {
        const float wh = hW[kk * cD + d];
        const float wg = gW[kk * cD + d];
        const float wk = kW[kk * cD + d];
#pragma unroll
        for (int c = 0; c < cC; c++) {
            const float x = xs[c * cD + kk];
            accH[c] = fmaf(x, wh, accH[c]);
            accG[c] = fmaf(x, wg, accG[c]);
            accK[c] = fmaf(x, wk, accK[c]);
        }
    }
    const size_t base = (size_t)br * cCD + d;
#pragma unroll
    for (int c = 0; c < cC; c++) {
        g_Yh[base + c * cD] = accH[c];
        g_Yg[base + c * cD] = accG[c];
        g_Km[base + c * cD] = accK[c];
    }
}

// ---------------------------------------------------------------------------
// Kernel 2: main fused kernel. grid = (TILES, B), 512 threads, ~211KB dyn smem
// ---------------------------------------------------------------------------
__global__ __launch_bounds__(NT, 1) void phylo_main(
    const float* __restrict__ batch,
    const float* __restrict__ seq_mask,
    const int*   __restrict__ rowi,
    const int*   __restrict__ coli,
    const float* __restrict__ hb,
    const float* __restrict__ qW, const float* __restrict__ qb,
    const float* __restrict__ s1W, const float* __restrict__ s1b,
    const float* __restrict__ s2W, const float* __restrict__ s2b,
    float* __restrict__ out)
{
    extern __shared__ float sm[];
    float2* Wp   = (float2*)(sm + OFF_WS);    // paired weights (kp, d)
    float*  Xs   = sm + OFF_XS;
    float*  Al   = sm + OFF_AL;
    float2* Al2  = (float2*)(sm + OFF_AL2);   // duplicated alpha
    float*  hb_s = sm + OFF_HB;
    float*  qb_s = sm + OFF_QB;
    float*  s1b_s= sm + OFF_S1B;
    float*  s2w_s= sm + OFF_S2W;
    float*  msk_s= sm + OFF_MSK;
    float*  sc_s = sm + OFF_SC;
    int*    ri_s = (int*)(sm + OFF_RI);
    int*    ci_s = (int*)(sm + OFF_CI);

    const int tile = blockIdx.x;
    const int b    = blockIdx.y;
    const int tid  = threadIdx.x;
    const int wid  = tid >> 5;
    const int lane = tid & 31;
    const int cd   = tid * 4;        // 512*4 = 2048 = full CD
    const int d0   = cd & (cD - 1);

    // ---- init small smem + pack qW into paired layout ----
    if (tid < cD) {
        hb_s[tid]  = hb[tid];
        qb_s[tid]  = qb[tid];
        s1b_s[tid] = s1b[tid];
        s2w_s[tid] = s2W[tid];
    }
    if (tid < cC) msk_s[tid] = seq_mask[b * cC + tid];
    if (tid < cP) {
        const int n = tile * cP + tid;
        ri_s[tid] = rowi[n];
        ci_s[tid] = coli[n];
        sc_s[tid] = 0.0f;
    }
    if (tid == 0) sm[OFF_S2B] = s2b[0];
    for (int idx = tid; idx < 64 * cD; idx += NT) {
        const int kp = idx >> 7, d = idx & 127;
        Wp[idx] = make_float2(qW[(2 * kp) * cD + d], qW[(2 * kp + 1) * cD + d]);
    }
    __syncthreads();

    // ---- Stage 1: x_mid = z*x_i + (1-z)*x_j into Xs ----
    for (int p = 0; p < cP; p++) {
        const int ri = ri_s[p], ci = ci_s[p];
        const float* Yi = g_Yh + (b * cR + ri) * cCD;
        const float* Yj = g_Yh + (b * cR + ci) * cCD;
        const float* Xi = batch + (b * cR + ri) * cCD;
        const float* Xj = batch + (b * cR + ci) * cCD;
        float4 yi = *(const float4*)&Yi[cd];
        float4 yj = *(const float4*)&Yj[cd];
        float4 xi = *(const float4*)&Xi[cd];
        float4 xj = *(const float4*)&Xj[cd];
        float4 o;
        { float z = sigmoidf_(yi.x - yj.x + hb_s[d0 + 0]); o.x = z * xi.x + (1.0f - z) * xj.x; }
        { float z = sigmoidf_(yi.y - yj.y + hb_s[d0 + 1]); o.y = z * xi.y + (1.0f - z) * xj.y; }
        { float z = sigmoidf_(yi.z - yj.z + hb_s[d0 + 2]); o.z = z * xi.z + (1.0f - z) * xj.z; }
        { float z = sigmoidf_(yi.w - yj.w + hb_s[d0 + 3]); o.w = z * xi.w + (1.0f - z) * xj.w; }
        *(float4*)&Xs[p * cCD + cd] = o;
    }
    __syncthreads();

    // ---- Stage 2: q = x_mid @ qW + qb, in-place over Xs ----
    // Paired weights: one ulonglong2 = f32x2 pairs for two d-columns.
    for (int g = 0; g < 2; g++) {
        const int rbase = wid * 16 + g * 8;
        u64 acc[8][4];
#pragma unroll
        for (int rr = 0; rr < 8; rr++)
#pragma unroll
            for (int u = 0; u < 4; u++) acc[rr][u] = 0ull;
        for (int kp = 0; kp < 64; kp++) {
            const ulonglong2* wr = (const ulonglong2*)(Wp + kp * cD);
            ulonglong2 wa = wr[lane * 2 + 0];   // d = lane*4+0, +1
            ulonglong2 wb = wr[lane * 2 + 1];   // d = lane*4+2, +3
#pragma unroll
            for (int rr = 0; rr < 8; rr++) {
                u64 xp = *(u64*)&Xs[(rbase + rr) * cD + 2 * kp];   // LDS.64 broadcast
                acc[rr][0] = ffma2(xp, wa.x, acc[rr][0]);
                acc[rr][1] = ffma2(xp, wa.y, acc[rr][1]);
                acc[rr][2] = ffma2(xp, wb.x, acc[rr][2]);
                acc[rr][3] = ffma2(xp, wb.y, acc[rr][3]);
            }
        }
        __syncwarp();
#pragma unroll
        for (int rr = 0; rr < 8; rr++) {
            float4 o;
            float2 a0 = upk2(acc[rr][0]); o.x = a0.x + a0.y + qb_s[lane * 4 + 0];
            float2 a1 = upk2(acc[rr][1]); o.y = a1.x + a1.y + qb_s[lane * 4 + 1];
            float2 a2 = upk2(acc[rr][2]); o.z = a2.x + a2.y + qb_s[lane * 4 + 2];
            float2 a3 = upk2(acc[rr][3]); o.w = a3.x + a3.y + qb_s[lane * 4 + 3];
            *(float4*)&Xs[(rbase + rr) * cD + lane * 4] = o;
        }
        __syncwarp();
    }
    __syncthreads();

    // ---- Stage 3: alpha[p][r] = <q[p], K[b,r]>, packed along K ----
    {
        const int r = wid * 4 + (lane >> 3);   // 64 r over 16 warps
        const int s = lane & 7;                // 8 lanes per r
        const float* Kr = g_Km + (b * cR + r) * cCD;
        u64 acc[cP];
#pragma unroll
        for (int p = 0; p < cP; p++) acc[p] = 0ull;
#pragma unroll 2
        for (int i = s * 4; i < cCD; i += 32) {
            ulonglong2 kv = *(const ulonglong2*)&Kr[i];
#pragma unroll
            for (int p = 0; p < cP; p++) {
                ulonglong2 qv = *(ulonglong2*)&Xs[p * cCD + i];
                acc[p] = ffma2(kv.x, qv.x, acc[p]);
                acc[p] = ffma2(kv.y, qv.y, acc[p]);
            }
        }
#pragma unroll
        for (int p = 0; p < cP; p++) {
            float2 t = upk2(acc[p]);
            float v = t.x + t.y;
            v += __shfl_xor_sync(0xffffffffu, v, 1);
            v += __shfl_xor_sync(0xffffffffu, v, 2);
            v += __shfl_xor_sync(0xffffffffu, v, 4);
            if (s == 0) Al[p * cR + r] = v;
        }
    }
    __syncthreads();

    // ---- Stage 4: masked softmax -> duplicated Al2; also pack s1W over qW ----
    {
        const float scale = rsqrtf((float)(cD * cC));
        const int p = wid;
        const int ri = ri_s[p], ci = ci_s[p];
        float v0 = Al[p * cR + lane];
        float v1 = Al[p * cR + lane + 32];
        v0 = (lane == ri || lane == ci) ? -INFINITY : v0 * scale;
        const int l2 = lane + 32;
        v1 = (l2 == ri || l2 == ci) ? -INFINITY : v1 * scale;
        float mx = fmaxf(v0, v1);
#pragma unroll
        for (int o = 16; o; o >>= 1) mx = fmaxf(mx, __shfl_xor_sync(0xffffffffu, mx, o));
        float e0 = __expf(v0 - mx);
        float e1 = __expf(v1 - mx);
        float sum = e0 + e1;
#pragma unroll
        for (int o = 16; o; o >>= 1) sum += __shfl_xor_sync(0xffffffffu, sum, o);
        const float inv = 1.0f / sum;
        const float a0 = e0 * inv, a1 = e1 * inv;
        Al2[p * cR + lane]      = make_float2(a0, a0);
        Al2[p * cR + lane + 32] = make_float2(a1, a1);
    }
    // Ws is dead after stage 2: repack with s1W under the same barrier.
    for (int idx = tid; idx < 64 * cD; idx += NT) {
        const int kp = idx >> 7, d = idx & 127;
        Wp[idx] = make_float2(s1W[(2 * kp) * cD + d], s1W[(2 * kp + 1) * cD + d]);
    }
    __syncthreads();

    // ---- Stage 5+6: x_glob & g accumulation (all 16 p, one r sweep per half),
    //      recompute x_mid, blend -> Xs ----
    {
        const float* Bb = batch + b * cR * cCD;
        const float* Gg = g_Yg + b * cR * cCD;
        const u64* Al2u = (const u64*)Al2;
        for (int ch = 0; ch < 2; ch++) {
            const int cdx = ch * 1024 + tid * 2;
            const int dx  = cdx & (cD - 1);
            u64 ax[cP], ag[cP];
#pragma unroll
            for (int pp = 0; pp < cP; pp++) { ax[pp] = 0ull; ag[pp] = 0ull; }
            for (int r = 0; r < cR; r++) {
                u64 bv = *(const u64*)&Bb[r * cCD + cdx];
                u64 gv = *(const u64*)&Gg[r * cCD + cdx];
#pragma unroll
                for (int pp = 0; pp < cP; pp++) {
                    u64 a2 = Al2u[pp * cR + r];     // LDS.64 all-lane broadcast
                    ax[pp] = ffma2(a2, bv, ax[pp]);
                    ag[pp] = ffma2(a2, gv, ag[pp]);
                }
            }
#pragma unroll
            for (int pp = 0; pp < cP; pp++) {
                const int ri = ri_s[pp], ci = ci_s[pp];
                float2 yi = *(const float2*)&g_Yh[(b * cR + ri) * cCD + cdx];
                float2 yj = *(const float2*)&g_Yh[(b * cR + ci) * cCD + cdx];
                float2 xi = *(const float2*)&batch[(b * cR + ri) * cCD + cdx];
                float2 xj = *(const float2*)&batch[(b * cR + ci) * cCD + cdx];
                float2 xg = upk2(ax[pp]);
                float2 gg = upk2(ag[pp]);
                float2 xf;
                {
                    float z  = sigmoidf_(yi.x - yj.x + hb_s[dx + 0]);
                    float xm = z * xi.x + (1.0f - z) * xj.x;
                    float w  = sigmoidf_(gg.x);
                    xf.x = (1.0f - w) * xm + w * xg.x;
                }
                {
                    float z  = sigmoidf_(yi.y - yj.y + hb_s[dx + 1]);
                    float xm = z * xi.y + (1.0f - z) * xj.y;
                    float w  = sigmoidf_(gg.y);
                    xf.y = (1.0f - w) * xm + w * xg.y;
                }
                *(float2*)&Xs[pp * cCD + cdx] = xf;
            }
        }
    }
    __syncthreads();

    // ---- Stage 7: s = gelu(x@s1W+s1b)@s2W + s2b ; scores[p] += s*mask[c] ----
    {
        const float s2bv = sm[OFF_S2B];
        for (int g = 0; g < 2; g++) {
            const int rbase = wid * 16 + g * 8;
            u64 acc[8][4];
#pragma unroll
            for (int rr = 0; rr < 8; rr++)
#pragma unroll
                for (int u = 0; u < 4; u++) acc[rr][u] = 0ull;
            for (int kp = 0; kp < 64; kp++) {
                const ulonglong2* wr = (const ulonglong2*)(Wp + kp * cD);
                ulonglong2 wa = wr[lane * 2 + 0];
                ulonglong2 wb = wr[lane * 2 + 1];
#pragma unroll
                for (int rr = 0; rr < 8; rr++) {
                    u64 xp = *(u64*)&Xs[(rbase + rr) * cD + 2 * kp];
                    acc[rr][0] = ffma2(xp, wa.x, acc[rr][0]);
                    acc[rr][1] = ffma2(xp, wa.y, acc[rr][1]);
                    acc[rr][2] = ffma2(xp, wb.x, acc[rr][2]);
                    acc[rr][3] = ffma2(xp, wb.y, acc[rr][3]);
                }
            }
#pragma unroll
            for (int rr = 0; rr < 8; rr++) {
                float part = 0.0f;
#pragma unroll
                for (int u = 0; u < 4; u++) {
                    float2 a = upk2(acc[rr][u]);
                    const float t = a.x + a.y + s1b_s[lane * 4 + u];
                    const float ge = 0.5f * t * (1.0f + erff(t * 0.70710678118654752f));
                    part = fmaf(ge, s2w_s[lane * 4 + u], part);
                }
#pragma unroll
                for (int o = 16; o; o >>= 1) part += __shfl_xor_sync(0xffffffffu, part, o);
                if (lane == 0) {
                    const int row = rbase + rr;
                    const int p = row >> 4, c = row & 15;
                    atomicAdd(&sc_s[p], (part + s2bv) * msk_s[c]);
                }
            }
        }
    }
    __syncthreads();

    if (tid < cP) out[b * cN + tile * cP + tid] = sc_s[tid];
}

// ---------------------------------------------------------------------------
extern "C" void kernel_launch(void* const* d_in, const int* in_sizes, int n_in,
                              void* d_out, int out_size)
{
    const float* batch    = (const float*)d_in[0];
    const float* seq_mask = (const float*)d_in[1];
    const int*   rowi     = (const int*)d_in[2];
    const int*   coli     = (const int*)d_in[3];
    const float* hW       = (const float*)d_in[4];
    const float* hb       = (const float*)d_in[5];
    const float* gW       = (const float*)d_in[6];
    const float* gb       = (const float*)d_in[7];
    const float* qW       = (const float*)d_in[8];
    const float* qb       = (const float*)d_in[9];
    const float* kW       = (const float*)d_in[10];
    const float* kb       = (const float*)d_in[11];
    const float* s1W      = (const float*)d_in[12];
    const float* s1b      = (const float*)d_in[13];
    const float* s2W      = (const float*)d_in[14];
    const float* s2b      = (const float*)d_in[15];
    float* out = (float*)d_out;

    cudaFuncSetAttribute(phylo_main, cudaFuncAttributeMaxDynamicSharedMemorySize, SMEM_BYTES);

    phylo_precompute<<<cB * cR, 128>>>(batch, hW, gW, gb, kW, kb);
    phylo_main<<<dim3(cTILES, cB), NT, SMEM_BYTES>>>(
        batch, seq_mask, rowi, coli, hb, qW, qb, s1W, s1b, s2W, s2b, out);
}

// round 7
// speedup vs baseline: 1.5401x; 1.5401x over previous
#include <cuda_runtime.h>
#include <math.h>

// Problem constants
constexpr int cB = 8;
constexpr int cR = 64;
constexpr int cC = 16;
constexpr int cD = 128;
constexpr int cN = 2016;          // R*(R-1)/2
constexpr int cCD = cC * cD;      // 2048
constexpr int cP = 16;            // pairs per CTA
constexpr int cTILES = cN / cP;   // 126
constexpr int NT = 512;           // 16 warps

// Scratch (allocation-free rule: __device__ globals)
__device__ float g_Yh[(size_t)cB * cR * cCD];   // batch @ hW          (4MB)
__device__ float g_Yg[(size_t)cB * cR * cCD];   // batch @ gW + gb     (4MB)
__device__ float g_Km[(size_t)cB * cR * cCD];   // batch @ kW + kb     (4MB)

// Shared memory layout (float offsets)
constexpr int OFF_WS  = 0;                  // 64x128 float2 paired weights (16384 floats)
constexpr int OFF_XS  = OFF_WS + cD * cD;   // 16384 : P*CD tile (x_mid -> q -> x_final)
constexpr int OFF_AL  = OFF_XS + cP * cCD;  // 49152 : alpha P*R
constexpr int OFF_HB  = OFF_AL + cP * cR;   // 50176
constexpr int OFF_QB  = OFF_HB + cD;
constexpr int OFF_S1B = OFF_QB + cD;
constexpr int OFF_S2W = OFF_S1B + cD;
constexpr int OFF_MSK = OFF_S2W + cD;
constexpr int OFF_SC  = OFF_MSK + cC;
constexpr int OFF_RI  = OFF_SC + cP;
constexpr int OFF_CI  = OFF_RI + cP;
constexpr int OFF_S2B = OFF_CI + cP;
constexpr int SMEM_FLOATS = OFF_S2B + 8;
constexpr int SMEM_BYTES  = SMEM_FLOATS * 4;   // ~203 KB

typedef unsigned long long u64;

__device__ __forceinline__ float sigmoidf_(float x) { return 1.0f / (1.0f + __expf(-x)); }

__device__ __forceinline__ u64 pk2(float lo, float hi) {
    u64 r; asm("mov.b64 %0,{%1,%2};" : "=l"(r) : "f"(lo), "f"(hi)); return r;
}
__device__ __forceinline__ float2 upk2(u64 v) {
    float2 f; asm("mov.b64 {%0,%1},%2;" : "=f"(f.x), "=f"(f.y) : "l"(v)); return f;
}
__device__ __forceinline__ u64 ffma2(u64 a, u64 b, u64 c) {
    u64 d; asm("fma.rn.f32x2 %0,%1,%2,%3;" : "=l"(d) : "l"(a), "l"(b), "l"(c)); return d;
}

// ---------------------------------------------------------------------------
// Kernel 1: precompute Yh = batch@hW, Yg = batch@gW + gb, Km = batch@kW + kb
// ---------------------------------------------------------------------------
__global__ __launch_bounds__(128) void phylo_precompute(
    const float* __restrict__ batch,
    const float* __restrict__ hW,
    const float* __restrict__ gW, const float* __restrict__ gb,
    const float* __restrict__ kW, const float* __restrict__ kb)
{
    __shared__ float xs[cCD];
    const int br  = blockIdx.x;
    const int tid = threadIdx.x;
    const float* src = batch + (size_t)br * cCD;
    for (int i = tid; i < cCD; i += 128) xs[i] = src[i];
    __syncthreads();

    const int d = tid;
    float accH[cC], accG[cC], accK[cC];
    const float gbd = gb[d], kbd = kb[d];
#pragma unroll
    for (int c = 0; c < cC; c++) { accH[c] = 0.0f; accG[c] = gbd; accK[c] = kbd; }

    for (int kk = 0; kk < cD; kk++) {
        const float wh = hW[kk * cD + d];
        const float wg = gW[kk * cD + d];
        const float wk = kW[kk * cD + d];
#pragma unroll
        for (int c = 0; c < cC; c++) {
            const float x = xs[c * cD + kk];
            accH[c] = fmaf(x, wh, accH[c]);
            accG[c] = fmaf(x, wg, accG[c]);
            accK[c] = fmaf(x, wk, accK[c]);
        }
    }
    const size_t base = (size_t)br * cCD + d;
#pragma unroll
    for (int c = 0; c < cC; c++) {
        g_Yh[base + c * cD] = accH[c];
        g_Yg[base + c * cD] = accG[c];
        g_Km[base + c * cD] = accK[c];
    }
}

// ---------------------------------------------------------------------------
// Kernel 2: main fused kernel. grid = (TILES, B), 512 threads, ~203KB dyn smem
// ---------------------------------------------------------------------------
__global__ __launch_bounds__(NT, 1) void phylo_main(
    const float* __restrict__ batch,
    const float* __restrict__ seq_mask,
    const int*   __restrict__ rowi,
    const int*   __restrict__ coli,
    const float* __restrict__ hb,
    const float* __restrict__ qW, const float* __restrict__ qb,
    const float* __restrict__ s1W, const float* __restrict__ s1b,
    const float* __restrict__ s2W, const float* __restrict__ s2b,
    float* __restrict__ out)
{
    extern __shared__ float sm[];
    float2* Wp   = (float2*)(sm + OFF_WS);    // paired weights: Wp[kp*cD+d] = (W[2kp][d], W[2kp+1][d])
    float*  Xs   = sm + OFF_XS;
    float*  Al   = sm + OFF_AL;
    float*  hb_s = sm + OFF_HB;
    float*  qb_s = sm + OFF_QB;
    float*  s1b_s= sm + OFF_S1B;
    float*  s2w_s= sm + OFF_S2W;
    float*  msk_s= sm + OFF_MSK;
    float*  sc_s = sm + OFF_SC;
    int*    ri_s = (int*)(sm + OFF_RI);
    int*    ci_s = (int*)(sm + OFF_CI);

    const int tile = blockIdx.x;
    const int b    = blockIdx.y;
    const int tid  = threadIdx.x;
    const int wid  = tid >> 5;
    const int lane = tid & 31;
    const int cd   = tid * 4;        // 512*4 = 2048 = full CD
    const int d0   = cd & (cD - 1);

    // ---- init small smem + pack qW into paired layout ----
    if (tid < cD) {
        hb_s[tid]  = hb[tid];
        qb_s[tid]  = qb[tid];
        s1b_s[tid] = s1b[tid];
        s2w_s[tid] = s2W[tid];
    }
    if (tid < cC) msk_s[tid] = seq_mask[b * cC + tid];
    if (tid < cP) {
        const int n = tile * cP + tid;
        ri_s[tid] = rowi[n];
        ci_s[tid] = coli[n];
        sc_s[tid] = 0.0f;
    }
    if (tid == 0) sm[OFF_S2B] = s2b[0];
    for (int idx = tid; idx < 64 * cD; idx += NT) {
        const int kp = idx >> 7, d = idx & 127;
        Wp[idx] = make_float2(qW[(2 * kp) * cD + d], qW[(2 * kp + 1) * cD + d]);
    }
    __syncthreads();

    // ---- Stage 1: x_mid = z*x_i + (1-z)*x_j into Xs ----
    for (int p = 0; p < cP; p++) {
        const int ri = ri_s[p], ci = ci_s[p];
        const float* Yi = g_Yh + (b * cR + ri) * cCD;
        const float* Yj = g_Yh + (b * cR + ci) * cCD;
        const float* Xi = batch + (b * cR + ri) * cCD;
        const float* Xj = batch + (b * cR + ci) * cCD;
        float4 yi = *(const float4*)&Yi[cd];
        float4 yj = *(const float4*)&Yj[cd];
        float4 xi = *(const float4*)&Xi[cd];
        float4 xj = *(const float4*)&Xj[cd];
        float4 o;
        { float z = sigmoidf_(yi.x - yj.x + hb_s[d0 + 0]); o.x = z * xi.x + (1.0f - z) * xj.x; }
        { float z = sigmoidf_(yi.y - yj.y + hb_s[d0 + 1]); o.y = z * xi.y + (1.0f - z) * xj.y; }
        { float z = sigmoidf_(yi.z - yj.z + hb_s[d0 + 2]); o.z = z * xi.z + (1.0f - z) * xj.z; }
        { float z = sigmoidf_(yi.w - yj.w + hb_s[d0 + 3]); o.w = z * xi.w + (1.0f - z) * xj.w; }
        *(float4*)&Xs[p * cCD + cd] = o;
    }
    __syncthreads();

    // ---- Stage 2: q = x_mid @ qW + qb, in-place over Xs ----
    // kq step covers TWO k-pairs: one LDS.128 broadcast of X per row serves both.
    for (int g = 0; g < 2; g++) {
        const int rbase = wid * 16 + g * 8;
        u64 acc[8][4];
#pragma unroll
        for (int rr = 0; rr < 8; rr++)
#pragma unroll
            for (int u = 0; u < 4; u++) acc[rr][u] = 0ull;
        for (int kq = 0; kq < 32; kq++) {
            const ulonglong2* w0 = (const ulonglong2*)(Wp + (2 * kq) * cD);
            const ulonglong2* w1 = (const ulonglong2*)(Wp + (2 * kq + 1) * cD);
            ulonglong2 wa0 = w0[lane * 2 + 0];   // kp=2kq, d = lane*4+{0,1}
            ulonglong2 wb0 = w0[lane * 2 + 1];   // kp=2kq, d = lane*4+{2,3}
            ulonglong2 wa1 = w1[lane * 2 + 0];   // kp=2kq+1
            ulonglong2 wb1 = w1[lane * 2 + 1];
#pragma unroll
            for (int rr = 0; rr < 8; rr++) {
                ulonglong2 xq = *(ulonglong2*)&Xs[(rbase + rr) * cD + 4 * kq]; // LDS.128 bcast
                acc[rr][0] = ffma2(xq.x, wa0.x, acc[rr][0]);
                acc[rr][1] = ffma2(xq.x, wa0.y, acc[rr][1]);
                acc[rr][2] = ffma2(xq.x, wb0.x, acc[rr][2]);
                acc[rr][3] = ffma2(xq.x, wb0.y, acc[rr][3]);
                acc[rr][0] = ffma2(xq.y, wa1.x, acc[rr][0]);
                acc[rr][1] = ffma2(xq.y, wa1.y, acc[rr][1]);
                acc[rr][2] = ffma2(xq.y, wb1.x, acc[rr][2]);
                acc[rr][3] = ffma2(xq.y, wb1.y, acc[rr][3]);
            }
        }
        __syncwarp();
#pragma unroll
        for (int rr = 0; rr < 8; rr++) {
            float4 o;
            float2 a0 = upk2(acc[rr][0]); o.x = a0.x + a0.y + qb_s[lane * 4 + 0];
            float2 a1 = upk2(acc[rr][1]); o.y = a1.x + a1.y + qb_s[lane * 4 + 1];
            float2 a2 = upk2(acc[rr][2]); o.z = a2.x + a2.y + qb_s[lane * 4 + 2];
            float2 a3 = upk2(acc[rr][3]); o.w = a3.x + a3.y + qb_s[lane * 4 + 3];
            *(float4*)&Xs[(rbase + rr) * cD + lane * 4] = o;
        }
        __syncwarp();
    }
    __syncthreads();

    // ---- Stage 3: alpha[p][r] = <q[p], K[b,r]>, packed along K ----
    {
        const int r = wid * 4 + (lane >> 3);   // 64 r over 16 warps
        const int s = lane & 7;                // 8 lanes per r
        const float* Kr = g_Km + (b * cR + r) * cCD;
        u64 acc[cP];
#pragma unroll
        for (int p = 0; p < cP; p++) acc[p] = 0ull;
#pragma unroll 2
        for (int i = s * 4; i < cCD; i += 32) {
            ulonglong2 kv = *(const ulonglong2*)&Kr[i];
#pragma unroll
            for (int p = 0; p < cP; p++) {
                ulonglong2 qv = *(ulonglong2*)&Xs[p * cCD + i];
                acc[p] = ffma2(kv.x, qv.x, acc[p]);
                acc[p] = ffma2(kv.y, qv.y, acc[p]);
            }
        }
#pragma unroll
        for (int p = 0; p < cP; p++) {
            float2 t = upk2(acc[p]);
            float v = t.x + t.y;
            v += __shfl_xor_sync(0xffffffffu, v, 1);
            v += __shfl_xor_sync(0xffffffffu, v, 2);
            v += __shfl_xor_sync(0xffffffffu, v, 4);
            if (s == 0) Al[p * cR + r] = v;
        }
    }
    __syncthreads();

    // ---- Stage 4: masked softmax over r; also repack s1W over dead qW ----
    {
        const float scale = rsqrtf((float)(cD * cC));
        const int p = wid;
        const int ri = ri_s[p], ci = ci_s[p];
        float v0 = Al[p * cR + lane];
        float v1 = Al[p * cR + lane + 32];
        v0 = (lane == ri || lane == ci) ? -INFINITY : v0 * scale;
        const int l2 = lane + 32;
        v1 = (l2 == ri || l2 == ci) ? -INFINITY : v1 * scale;
        float mx = fmaxf(v0, v1);
#pragma unroll
        for (int o = 16; o; o >>= 1) mx = fmaxf(mx, __shfl_xor_sync(0xffffffffu, mx, o));
        float e0 = __expf(v0 - mx);
        float e1 = __expf(v1 - mx);
        float sum = e0 + e1;
#pragma unroll
        for (int o = 16; o; o >>= 1) sum += __shfl_xor_sync(0xffffffffu, sum, o);
        const float inv = 1.0f / sum;
        Al[p * cR + lane]      = e0 * inv;
        Al[p * cR + lane + 32] = e1 * inv;
    }
    for (int idx = tid; idx < 64 * cD; idx += NT) {
        const int kp = idx >> 7, d = idx & 127;
        Wp[idx] = make_float2(s1W[(2 * kp) * cD + d], s1W[(2 * kp + 1) * cD + d]);
    }
    __syncthreads();

    // ---- Stage 5+6: x_glob & g accumulation (2 phases x 8 pairs, 128-bit),
    //      recompute x_mid, blend -> Xs ----
    {
        const float* Bb = batch + b * cR * cCD;
        const float* Gg = g_Yg + b * cR * cCD;
        for (int ph = 0; ph < 2; ph++) {
            u64 ax0[8], ax1[8], ag0[8], ag1[8];
#pragma unroll
            for (int pp = 0; pp < 8; pp++) { ax0[pp] = ax1[pp] = ag0[pp] = ag1[pp] = 0ull; }
            for (int r = 0; r < cR; r++) {
                ulonglong2 bv = *(const ulonglong2*)&Bb[r * cCD + cd];
                ulonglong2 gv = *(const ulonglong2*)&Gg[r * cCD + cd];
#pragma unroll
                for (int pp = 0; pp < 8; pp++) {
                    const float a = Al[(ph * 8 + pp) * cR + r];   // LDS.32 broadcast
                    const u64 a2 = pk2(a, a);
                    ax0[pp] = ffma2(a2, bv.x, ax0[pp]);
                    ax1[pp] = ffma2(a2, bv.y, ax1[pp]);
                    ag0[pp] = ffma2(a2, gv.x, ag0[pp]);
                    ag1[pp] = ffma2(a2, gv.y, ag1[pp]);
                }
            }
#pragma unroll
            for (int pp = 0; pp < 8; pp++) {
                const int p = ph * 8 + pp;
                const int ri = ri_s[p], ci = ci_s[p];
                float4 yi = *(const float4*)&g_Yh[(b * cR + ri) * cCD + cd];
                float4 yj = *(const float4*)&g_Yh[(b * cR + ci) * cCD + cd];
                float4 xi = *(const float4*)&batch[(b * cR + ri) * cCD + cd];
                float4 xj = *(const float4*)&batch[(b * cR + ci) * cCD + cd];
                float2 x0 = upk2(ax0[pp]), x1 = upk2(ax1[pp]);
                float2 g0 = upk2(ag0[pp]), g1 = upk2(ag1[pp]);
                float4 xf;
                {
                    float z = sigmoidf_(yi.x - yj.x + hb_s[d0 + 0]);
                    float xm = z * xi.x + (1.0f - z) * xj.x;
                    float w = sigmoidf_(g0.x);
                    xf.x = (1.0f - w) * xm + w * x0.x;
                }
                {
                    float z = sigmoidf_(yi.y - yj.y + hb_s[d0 + 1]);
                    float xm = z * xi.y + (1.0f - z) * xj.y;
                    float w = sigmoidf_(g0.y);
                    xf.y = (1.0f - w) * xm + w * x0.y;
                }
                {
                    float z = sigmoidf_(yi.z - yj.z + hb_s[d0 + 2]);
                    float xm = z * xi.z + (1.0f - z) * xj.z;
                    float w = sigmoidf_(g1.x);
                    xf.z = (1.0f - w) * xm + w * x1.x;
                }
                {
                    float z = sigmoidf_(yi.w - yj.w + hb_s[d0 + 3]);
                    float xm = z * xi.w + (1.0f - z) * xj.w;
                    float w = sigmoidf_(g1.y);
                    xf.w = (1.0f - w) * xm + w * x1.y;
                }
                *(float4*)&Xs[p * cCD + cd] = xf;
            }
        }
    }
    __syncthreads();

    // ---- Stage 7: s = gelu(x@s1W+s1b)@s2W + s2b ; scores[p] += s*mask[c] ----
    {
        const float s2bv = sm[OFF_S2B];
        for (int g = 0; g < 2; g++) {
            const int rbase = wid * 16 + g * 8;
            u64 acc[8][4];
#pragma unroll
            for (int rr = 0; rr < 8; rr++)
#pragma unroll
                for (int u = 0; u < 4; u++) acc[rr][u] = 0ull;
            for (int kq = 0; kq < 32; kq++) {
                const ulonglong2* w0 = (const ulonglong2*)(Wp + (2 * kq) * cD);
                const ulonglong2* w1 = (const ulonglong2*)(Wp + (2 * kq + 1) * cD);
                ulonglong2 wa0 = w0[lane * 2 + 0];
                ulonglong2 wb0 = w0[lane * 2 + 1];
                ulonglong2 wa1 = w1[lane * 2 + 0];
                ulonglong2 wb1 = w1[lane * 2 + 1];
#pragma unroll
                for (int rr = 0; rr < 8; rr++) {
                    ulonglong2 xq = *(ulonglong2*)&Xs[(rbase + rr) * cD + 4 * kq];
                    acc[rr][0] = ffma2(xq.x, wa0.x, acc[rr][0]);
                    acc[rr][1] = ffma2(xq.x, wa0.y, acc[rr][1]);
                    acc[rr][2] = ffma2(xq.x, wb0.x, acc[rr][2]);
                    acc[rr][3] = ffma2(xq.x, wb0.y, acc[rr][3]);
                    acc[rr][0] = ffma2(xq.y, wa1.x, acc[rr][0]);
                    acc[rr][1] = ffma2(xq.y, wa1.y, acc[rr][1]);
                    acc[rr][2] = ffma2(xq.y, wb1.x, acc[rr][2]);
                    acc[rr][3] = ffma2(xq.y, wb1.y, acc[rr][3]);
                }
            }
#pragma unroll
            for (int rr = 0; rr < 8; rr++) {
                float part = 0.0f;
#pragma unroll
                for (int u = 0; u < 4; u++) {
                    float2 a = upk2(acc[rr][u]);
                    const float t = a.x + a.y + s1b_s[lane * 4 + u];
                    const float ge = 0.5f * t * (1.0f + erff(t * 0.70710678118654752f));
                    part = fmaf(ge, s2w_s[lane * 4 + u], part);
                }
#pragma unroll
                for (int o = 16; o; o >>= 1) part += __shfl_xor_sync(0xffffffffu, part, o);
                if (lane == 0) {
                    const int row = rbase + rr;
                    const int p = row >> 4, c = row & 15;
                    atomicAdd(&sc_s[p], (part + s2bv) * msk_s[c]);
                }
            }
        }
    }
    __syncthreads();

    if (tid < cP) out[b * cN + tile * cP + tid] = sc_s[tid];
}

// ---------------------------------------------------------------------------
extern "C" void kernel_launch(void* const* d_in, const int* in_sizes, int n_in,
                              void* d_out, int out_size)
{
    const float* batch    = (const float*)d_in[0];
    const float* seq_mask = (const float*)d_in[1];
    const int*   rowi     = (const int*)d_in[2];
    const int*   coli     = (const int*)d_in[3];
    const float* hW       = (const float*)d_in[4];
    const float* hb       = (const float*)d_in[5];
    const float* gW       = (const float*)d_in[6];
    const float* gb       = (const float*)d_in[7];
    const float* qW       = (const float*)d_in[8];
    const float* qb       = (const float*)d_in[9];
    const float* kW       = (const float*)d_in[10];
    const float* kb       = (const float*)d_in[11];
    const float* s1W      = (const float*)d_in[12];
    const float* s1b      = (const float*)d_in[13];
    const float* s2W      = (const float*)d_in[14];
    const float* s2b      = (const float*)d_in[15];
    float* out = (float*)d_out;

    cudaFuncSetAttribute(phylo_main, cudaFuncAttributeMaxDynamicSharedMemorySize, SMEM_BYTES);

    phylo_precompute<<<cB * cR, 128>>>(batch, hW, gW, gb, kW, kb);
    phylo_main<<<dim3(cTILES, cB), NT, SMEM_BYTES>>>(
        batch, seq_mask, rowi, coli, hb, qW, qb, s1W, s1b, s2W, s2b, out);
}